// round 10
// baseline (speedup 1.0000x reference)
#include <cuda_runtime.h>
#include <cstdint>
#include <cmath>

#define NLEAF 128
#define NLOOP 128
#define BLOCK 128
#define NVAR  11
#define NGRP  32          // NLEAF/4 groups per order

typedef unsigned long long u64;

struct KParams {
  float KF, MAXK, BETA, MU, E0EPS, SCALE, PIB;
};

// ================= compile-time PERMS (numpy RandomState(0)) =================

struct Perms { int p[3][NLEAF]; };

__host__ __device__ constexpr uint32_t mt_temper(uint32_t y) {
  y ^= y >> 11;
  y ^= (y << 7)  & 0x9d2c5680u;
  y ^= (y << 15) & 0xefc60000u;
  y ^= y >> 18;
  return y;
}

__host__ __device__ constexpr Perms make_perms() {
  Perms P{};
  uint32_t mt[624] = {};
  mt[0] = 0u;                       // mt19937 init_genrand(0)
  for (int i = 1; i < 624; ++i)
    mt[i] = 1812433253u * (mt[i - 1] ^ (mt[i - 1] >> 30)) + (uint32_t)i;
  int idx = 624;
  for (int o = 0; o < 3; ++o) {
    int arr[NLEAF] = {};
    for (int i = 0; i < NLEAF; ++i) arr[i] = i;
    // numpy legacy shuffle: Fisher-Yates, random_interval mask-rejection
    for (int i = NLEAF - 1; i >= 1; --i) {
      uint32_t mask = (uint32_t)i;
      mask |= mask >> 1; mask |= mask >> 2; mask |= mask >> 4;
      mask |= mask >> 8; mask |= mask >> 16;
      uint32_t j = 0;
      while (true) {
        if (idx >= 624) {
          for (int k = 0; k < 624; ++k) {
            uint32_t y = (mt[k] & 0x80000000u) | (mt[(k + 1) % 624] & 0x7fffffffu);
            mt[k] = mt[(k + 397) % 624] ^ (y >> 1) ^ ((y & 1u) ? 0x9908b0dfu : 0u);
          }
          idx = 0;
        }
        j = mt_temper(mt[idx++]) & mask;
        if (j <= (uint32_t)i) break;
      }
      int t = arr[i]; arr[i] = arr[j]; arr[j] = t;
    }
    for (int k = 0; k < NLEAF; ++k) P.p[o][k] = arr[k];
  }
  return P;
}

// Inverse map: for each order and leaf, which group-of-4 it belongs to, and
// whether it is the first-produced (lowest-index) leaf of that group.
struct GMap { uint8_t grp[3][NLEAF]; uint8_t first[3][NLEAF]; };

__host__ __device__ constexpr GMap make_gmap() {
  Perms P = make_perms();
  GMap M{};
  for (int o = 0; o < 3; ++o) {
    for (int k = 0; k < NLEAF; ++k)
      M.grp[o][P.p[o][k]] = (uint8_t)(k / 4);
    bool seen[NGRP] = {};
    for (int lf = 0; lf < NLEAF; ++lf) {       // production order
      const int g = M.grp[o][lf];
      M.first[o][lf] = seen[g] ? 0 : 1;
      seen[g] = true;
    }
  }
  return M;
}

// ================= packed f32x2 helpers (FFMA2, PTX-only) =================

__device__ __forceinline__ u64 pk2(float lo, float hi) {
  u64 d; asm("mov.b64 %0, {%1, %2};" : "=l"(d) : "f"(lo), "f"(hi)); return d;
}
__device__ __forceinline__ void upk2(u64 d, float& lo, float& hi) {
  asm("mov.b64 {%0, %1}, %2;" : "=f"(lo), "=f"(hi) : "l"(d));
}
__device__ __forceinline__ u64 fma2(u64 a, u64 b, u64 c) {
  u64 d; asm("fma.rn.f32x2 %0, %1, %2, %3;" : "=l"(d) : "l"(a), "l"(b), "l"(c)); return d;
}
__device__ __forceinline__ u64 mul2(u64 a, u64 b) {
  u64 d; asm("mul.rn.f32x2 %0, %1, %2;" : "=l"(d) : "l"(a), "l"(b)); return d;
}

// scalar propagator evaluation for one leaf (warp-uniform branches)
__device__ __forceinline__ float leaf_eval(float kqx, float kq2, int m,
                                           float lb0, float v0, float v1,
                                           float BETAc, float MUc, float E0EPSc,
                                           const float* __restrict__ s_lv0, int lf)
{
  const int type = m & 3;
  if (type == 1) {
    const int ti = (m >> 2) & 3;
    const int to = (m >> 4) & 3;
    const float vi  = (ti == 0) ? 0.f : ((ti == 1) ? v0 : v1);
    const float vo  = (to == 0) ? 0.f : ((to == 1) ? v0 : v1);
    const float tau = (vo - vi) * BETAc;
    const float d   = kq2 - MUc;                  // kq2/(2*ME) - MU, ME = 0.5
    const bool  tp  = tau > 0.f;
    const bool  dp  = d   > 0.f;
    // flattened select form: shift = 0 when (tp==dp), else +-BETA
    const float shift = tp ? (dp ? 0.f : BETAc) : (dp ? -BETAc : 0.f);
    const float a     = shift - tau;              // equals reference's 'a' in all 4 cases
    const float bbv   = dp ? -BETAc : BETAc;
    const float e1  = __expf(d * a);              // arg <= 0 always
    const float e2  = __expf(d * bbv);            // arg <= 0 always
    float f = __fdividef(e1, 1.f + e2);
    f = tp ? f : -f;
    if (m & 256) f *= 2.f * kqx * lb0;            // ad_factor / ME, ME = 0.5
    return f;
  } else if (type == 2) {
    const float invK = __fdividef(1.f, kq2 + 0.5f);   // MASS2 = 0.5
    const int   lo1  = (m >> 6) & 3;
    const float t    = 0.5f * invK;
    const float powt = (lo1 == 0) ? 1.f : ((lo1 == 1) ? t : t * t);
    float bse = E0EPSc * invK * powt;
    if (m & 256) bse *= kqx * lb0 * invK * (-2.f) * (float)(lo1 + 1);
    return bse;
  }
  return s_lv0[lf];
}

__global__ void __launch_bounds__(BLOCK)
feyn_kernel(const float* __restrict__ var,
            const int*   __restrict__ lftype,
            const int*   __restrict__ lforders,
            const int*   __restrict__ taui_g,
            const int*   __restrict__ tauo_g,
            const int*   __restrict__ momidx,
            const float* __restrict__ loopBasis,
            const float* __restrict__ lv0_g,
            float* __restrict__ out,
            int batch,
            KParams P)
{
  // function-local constexpr: evaluated by the front-end, valid in device code
  // without --expt-relaxed-constexpr; all uses fold to immediates after unroll.
  constexpr GMap GM = make_gmap();

  __shared__ __align__(16) float s_lb0[NLEAF], s_lb1[NLEAF], s_lb2[NLEAF], s_lb3[NLEAF], s_lv0[NLEAF];
  __shared__ __align__(16) int   s_meta[NLEAF];

  const int tid = threadIdx.x;

  // ---- per-block leaf metadata (batch-uniform) ----
  {
    const int lf  = tid;          // BLOCK == NLEAF
    const int mom = momidx[lf];
    s_lb0[lf] = loopBasis[0 * NLOOP + mom];
    s_lb1[lf] = loopBasis[1 * NLOOP + mom];
    s_lb2[lf] = loopBasis[2 * NLOOP + mom];
    s_lb3[lf] = loopBasis[3 * NLOOP + mom];
    s_lv0[lf] = lv0_g[lf];
    const int lo1 = lforders[1 * NLEAF + lf];
    const int dk  = (lforders[2 * NLEAF + lf] == 1) ? 1 : 0;
    s_meta[lf] = (lftype[lf] & 3)
               | ((taui_g[lf] & 3) << 2)
               | ((tauo_g[lf] & 3) << 4)
               | ((lo1 & 3) << 6)
               | (dk << 8);
  }
  __syncthreads();

  const int  b  = blockIdx.x * BLOCK + tid;
  const int  bb = (b < batch) ? b : (batch - 1);
  const float* v = var + (long long)bb * NVAR;

  const float PI_F = 3.14159265358979323846f;

  const float v0 = v[0];
  const float v1 = v[1];

  float px[3], py[3], pz[3];
  float factor = 1.f;
  #pragma unroll
  for (int l = 0; l < 3; ++l) {
    const float pr = v[2 + l] * P.MAXK;
    const float th = v[5 + l] * PI_F;
    const float ph = v[8 + l] * (2.f * PI_F);
    float st, ct, sp, cp;
    __sincosf(th, &st, &ct);
    __sincosf(ph, &sp, &cp);
    px[l] = pr * st * cp;
    py[l] = pr * st * sp;
    pz[l] = pr * ct;
    factor *= pr * pr * st;
  }
  const float outscale = factor * P.SCALE;

  const float BETAc  = P.BETA;
  const float MUc    = P.MU;
  const float E0EPSc = P.E0EPS;

  // broadcast packs for f32x2 math
  const u64 px0 = pk2(px[0], px[0]), px1 = pk2(px[1], px[1]), px2_ = pk2(px[2], px[2]);
  const u64 py0 = pk2(py[0], py[0]), py1 = pk2(py[1], py[1]), py2_ = pk2(py[2], py[2]);
  const u64 pz0 = pk2(pz[0], pz[0]), pz1 = pk2(pz[1], pz[1]), pz2_ = pk2(pz[2], pz[2]);
  const u64 KF2 = pk2(P.KF, P.KF);

  // ---- leaf evaluation with ONLINE group-product accumulation ----
  // acc[o][g] = product of the 4 leaves in group g of order o (first-assign, then mul)
  float acc[3][NGRP];

  #pragma unroll
  for (int j = 0; j < NLEAF / 2; ++j) {
    const int lf = 2 * j;
    const u64 lb0 = *reinterpret_cast<const u64*>(&s_lb0[lf]);   // LDS.64 coeff pair
    const u64 lb1 = *reinterpret_cast<const u64*>(&s_lb1[lf]);
    const u64 lb2 = *reinterpret_cast<const u64*>(&s_lb2[lf]);
    const u64 lb3 = *reinterpret_cast<const u64*>(&s_lb3[lf]);
    const int2 mp = *reinterpret_cast<const int2*>(&s_meta[lf]);

    const u64 kqx2 = fma2(px2_, lb3, fma2(px1, lb2, fma2(px0, lb1, mul2(KF2, lb0))));
    const u64 kqy2 = fma2(py2_, lb3, fma2(py1, lb2, mul2(py0, lb1)));
    const u64 kqz2 = fma2(pz2_, lb3, fma2(pz1, lb2, mul2(pz0, lb1)));
    const u64 kq22 = fma2(kqx2, kqx2, fma2(kqy2, kqy2, mul2(kqz2, kqz2)));

    float kqxA, kqxB, kq2A, kq2B, lb0A, lb0B;
    upk2(kqx2, kqxA, kqxB);
    upk2(kq22, kq2A, kq2B);
    upk2(lb0,  lb0A, lb0B);

    const float vA = leaf_eval(kqxA, kq2A, mp.x, lb0A, v0, v1, BETAc, MUc, E0EPSc, s_lv0, lf);
    const float vB = leaf_eval(kqxB, kq2B, mp.y, lb0B, v0, v1, BETAc, MUc, E0EPSc, s_lv0, lf + 1);

    // fold into group accumulators (all indices compile-time after unroll)
    #pragma unroll
    for (int o = 0; o < 3; ++o) {
      const int gA = GM.grp[o][lf];
      if (GM.first[o][lf]) acc[o][gA] = vA; else acc[o][gA] *= vA;
      const int gB = GM.grp[o][lf + 1];
      if (GM.first[o][lf + 1]) acc[o][gB] = vB; else acc[o][gB] *= vB;
    }
  }

  // ---- final reduction over groups + phase ----
  const float ph1 = __cosf(P.PIB * v0);
  const float ph2 = __cosf(P.PIB * v1);
  float total = 0.f;
  #pragma unroll
  for (int o = 0; o < 3; ++o) {
    float s0 = 0.f, s1 = 0.f, s2 = 0.f, s3 = 0.f;   // 4-way tree: shorter dep chain
    #pragma unroll
    for (int g = 0; g < NGRP; g += 4) {
      s0 += acc[o][g];
      s1 += acc[o][g + 1];
      s2 += acc[o][g + 2];
      s3 += acc[o][g + 3];
    }
    const float s = (s0 + s1) + (s2 + s3);
    const float phase = (o == 0) ? 1.f : ((o == 1) ? ph1 : ph2);
    total = fmaf(s, phase, total);
  }

  if (b < batch)
    out[b] = total * outscale;
}

// ---------------- host side ----------------

extern "C" void kernel_launch(void* const* d_in, const int* in_sizes, int n_in,
                              void* d_out, int out_size)
{
  const float* var       = (const float*)d_in[0];
  // d_in[1] = root (unused by the reference)
  const int*   lftype    = (const int*)  d_in[2];
  const int*   lforders  = (const int*)  d_in[3];
  const int*   taui      = (const int*)  d_in[4];
  const int*   tauo      = (const int*)  d_in[5];
  const int*   momidx    = (const int*)  d_in[6];
  const float* loopBasis = (const float*)d_in[7];
  const float* lv0       = (const float*)d_in[8];
  float*       out       = (float*)d_out;

  const int batch = in_sizes[0] / NVAR;

  const double pi   = 3.14159265358979323846;
  const double kf   = pow(9.0 * pi / (2.0 * 2.0), 1.0 / 3.0) / 2.0;  // SPIN = 2
  const double ef   = kf * kf;                                        // KF^2/(2*ME), ME=0.5
  const double beta = 10.0 / ef;
  const double maxk = 10.0 * kf;

  KParams P;
  P.KF    = (float)kf;
  P.MAXK  = (float)maxk;
  P.BETA  = (float)beta;
  P.MU    = (float)(0.99177533 * ef);
  P.E0EPS = (float)(8.0 * pi);                                        // E0^2/EPS0 = 2*4pi
  P.SCALE = (float)(pow(maxk * 2.0 * pi * pi, 3.0) * beta * beta / pow(2.0 * pi, 9.0));
  P.PIB   = (float)(pi / beta);

  const int grid = (batch + BLOCK - 1) / BLOCK;
  feyn_kernel<<<grid, BLOCK>>>(var, lftype, lforders, taui, tauo, momidx,
                               loopBasis, lv0, out, batch, P);
}

// round 12
// speedup vs baseline: 1.4638x; 1.4638x over previous
#include <cuda_runtime.h>
#include <cstdint>
#include <cmath>

#define NLEAF 128
#define NLOOP 128
#define BLOCK 128
#define NVAR  11
#define NGRP  32          // NLEAF/4 groups per order

typedef unsigned long long u64;

struct KParams {
  float KF, MAXK, BETA, MU, E0EPS, SCALE, PIB;
};

// ================= compile-time PERMS (numpy RandomState(0)) =================

struct Perms { int p[3][NLEAF]; };

__host__ __device__ constexpr uint32_t mt_temper(uint32_t y) {
  y ^= y >> 11;
  y ^= (y << 7)  & 0x9d2c5680u;
  y ^= (y << 15) & 0xefc60000u;
  y ^= y >> 18;
  return y;
}

__host__ __device__ constexpr Perms make_perms() {
  Perms P{};
  uint32_t mt[624] = {};
  mt[0] = 0u;                       // mt19937 init_genrand(0)
  for (int i = 1; i < 624; ++i)
    mt[i] = 1812433253u * (mt[i - 1] ^ (mt[i - 1] >> 30)) + (uint32_t)i;
  int idx = 624;
  for (int o = 0; o < 3; ++o) {
    int arr[NLEAF] = {};
    for (int i = 0; i < NLEAF; ++i) arr[i] = i;
    // numpy legacy shuffle: Fisher-Yates, random_interval mask-rejection
    for (int i = NLEAF - 1; i >= 1; --i) {
      uint32_t mask = (uint32_t)i;
      mask |= mask >> 1; mask |= mask >> 2; mask |= mask >> 4;
      mask |= mask >> 8; mask |= mask >> 16;
      uint32_t j = 0;
      while (true) {
        if (idx >= 624) {
          for (int k = 0; k < 624; ++k) {
            uint32_t y = (mt[k] & 0x80000000u) | (mt[(k + 1) % 624] & 0x7fffffffu);
            mt[k] = mt[(k + 397) % 624] ^ (y >> 1) ^ ((y & 1u) ? 0x9908b0dfu : 0u);
          }
          idx = 0;
        }
        j = mt_temper(mt[idx++]) & mask;
        if (j <= (uint32_t)i) break;
      }
      int t = arr[i]; arr[i] = arr[j]; arr[j] = t;
    }
    for (int k = 0; k < NLEAF; ++k) P.p[o][k] = arr[k];
  }
  return P;
}

// Evaluation SEQUENCE = PERMS[0] order. For each sequence position k we record,
// per order o: the group id, and whether this position is the first / last
// member of that group encountered in the sequence. Groups close ASAP ->
// short accumulator live ranges -> far fewer pinned registers.
struct Seq {
  int     ord[NLEAF];          // leaf id evaluated at position k
  uint8_t grp[3][NLEAF];
  uint8_t first[3][NLEAF];
  uint8_t last[3][NLEAF];
};

__host__ __device__ constexpr Seq make_seq() {
  Perms P = make_perms();
  Seq S{};
  for (int k = 0; k < NLEAF; ++k) S.ord[k] = P.p[0][k];
  int lgrp[3][NLEAF] = {};
  for (int o = 0; o < 3; ++o)
    for (int k = 0; k < NLEAF; ++k) lgrp[o][P.p[o][k]] = k / 4;
  for (int o = 0; o < 3; ++o) {
    int cnt[NGRP] = {};
    for (int k = 0; k < NLEAF; ++k) {
      const int g = lgrp[o][S.ord[k]];
      S.grp[o][k]   = (uint8_t)g;
      S.first[o][k] = (uint8_t)(cnt[g] == 0 ? 1 : 0);
      cnt[g]++;
      S.last[o][k]  = (uint8_t)(cnt[g] == 4 ? 1 : 0);
    }
  }
  return S;
}

// Device-resident copy of the evaluation order for the (runtime-indexed) SMEM fill.
struct OrdArr { int v[NLEAF]; };
__host__ __device__ constexpr OrdArr make_ordarr() {
  Perms P = make_perms();
  OrdArr A{};
  for (int k = 0; k < NLEAF; ++k) A.v[k] = P.p[0][k];
  return A;
}
__device__ constexpr OrdArr D_ORD = make_ordarr();

// ================= packed f32x2 helpers (FFMA2, PTX-only) =================

__device__ __forceinline__ u64 pk2(float lo, float hi) {
  u64 d; asm("mov.b64 %0, {%1, %2};" : "=l"(d) : "f"(lo), "f"(hi)); return d;
}
__device__ __forceinline__ void upk2(u64 d, float& lo, float& hi) {
  asm("mov.b64 {%0, %1}, %2;" : "=f"(lo), "=f"(hi) : "l"(d));
}
__device__ __forceinline__ u64 fma2(u64 a, u64 b, u64 c) {
  u64 d; asm("fma.rn.f32x2 %0, %1, %2, %3;" : "=l"(d) : "l"(a), "l"(b), "l"(c)); return d;
}
__device__ __forceinline__ u64 mul2(u64 a, u64 b) {
  u64 d; asm("mul.rn.f32x2 %0, %1, %2;" : "=l"(d) : "l"(a), "l"(b)); return d;
}

// scalar propagator evaluation for one leaf (warp-uniform branches)
__device__ __forceinline__ float leaf_eval(float kqx, float kq2, int m,
                                           float lb0, float v0, float v1,
                                           float BETAc, float MUc, float E0EPSc,
                                           const float* __restrict__ s_lv0, int k)
{
  const int type = m & 3;
  if (type == 1) {
    const int ti = (m >> 2) & 3;
    const int to = (m >> 4) & 3;
    const float vi  = (ti == 0) ? 0.f : ((ti == 1) ? v0 : v1);
    const float vo  = (to == 0) ? 0.f : ((to == 1) ? v0 : v1);
    const float tau = (vo - vi) * BETAc;
    const float d   = kq2 - MUc;                  // kq2/(2*ME) - MU, ME = 0.5
    const bool  tp  = tau > 0.f;
    const bool  dp  = d   > 0.f;
    const float shift = tp ? (dp ? 0.f : BETAc) : (dp ? -BETAc : 0.f);
    const float a     = shift - tau;              // reference's 'a' in all 4 cases
    const float bbv   = dp ? -BETAc : BETAc;
    const float e1  = __expf(d * a);              // arg <= 0 always
    const float e2  = __expf(d * bbv);            // arg <= 0 always
    float f = __fdividef(e1, 1.f + e2);
    f = tp ? f : -f;
    if (m & 256) f *= 2.f * kqx * lb0;            // ad_factor / ME, ME = 0.5
    return f;
  } else if (type == 2) {
    const float invK = __fdividef(1.f, kq2 + 0.5f);   // MASS2 = 0.5
    const int   lo1  = (m >> 6) & 3;
    const float t    = 0.5f * invK;
    const float powt = (lo1 == 0) ? 1.f : ((lo1 == 1) ? t : t * t);
    float bse = E0EPSc * invK * powt;
    if (m & 256) bse *= kqx * lb0 * invK * (-2.f) * (float)(lo1 + 1);
    return bse;
  }
  return s_lv0[k];
}

__global__ void __launch_bounds__(BLOCK, 4)   // cap regs at 128 -> 16 warps/SM
feyn_kernel(const float* __restrict__ var,
            const int*   __restrict__ lftype,
            const int*   __restrict__ lforders,
            const int*   __restrict__ taui_g,
            const int*   __restrict__ tauo_g,
            const int*   __restrict__ momidx,
            const float* __restrict__ loopBasis,
            const float* __restrict__ lv0_g,
            float* __restrict__ out,
            int batch,
            KParams P)
{
  constexpr Seq SQ = make_seq();   // static indexing only -> folds to immediates

  __shared__ __align__(16) float s_lb0[NLEAF], s_lb1[NLEAF], s_lb2[NLEAF], s_lb3[NLEAF], s_lv0[NLEAF];
  __shared__ __align__(16) int   s_meta[NLEAF];

  const int tid = threadIdx.x;

  // ---- per-block leaf metadata, stored in EVALUATION ORDER ----
  {
    const int lf  = D_ORD.v[tid];     // leaf evaluated at sequence position tid
    const int mom = momidx[lf];
    s_lb0[tid] = loopBasis[0 * NLOOP + mom];
    s_lb1[tid] = loopBasis[1 * NLOOP + mom];
    s_lb2[tid] = loopBasis[2 * NLOOP + mom];
    s_lb3[tid] = loopBasis[3 * NLOOP + mom];
    s_lv0[tid] = lv0_g[lf];
    const int lo1 = lforders[1 * NLEAF + lf];
    const int dk  = (lforders[2 * NLEAF + lf] == 1) ? 1 : 0;
    s_meta[tid] = (lftype[lf] & 3)
                | ((taui_g[lf] & 3) << 2)
                | ((tauo_g[lf] & 3) << 4)
                | ((lo1 & 3) << 6)
                | (dk << 8);
  }
  __syncthreads();

  const int  b  = blockIdx.x * BLOCK + tid;
  const int  bb = (b < batch) ? b : (batch - 1);
  const float* v = var + (long long)bb * NVAR;

  const float PI_F = 3.14159265358979323846f;

  const float v0 = v[0];
  const float v1 = v[1];

  float px[3], py[3], pz[3];
  float factor = 1.f;
  #pragma unroll
  for (int l = 0; l < 3; ++l) {
    const float pr = v[2 + l] * P.MAXK;
    const float th = v[5 + l] * PI_F;
    const float ph = v[8 + l] * (2.f * PI_F);
    float st, ct, sp, cp;
    __sincosf(th, &st, &ct);
    __sincosf(ph, &sp, &cp);
    px[l] = pr * st * cp;
    py[l] = pr * st * sp;
    pz[l] = pr * ct;
    factor *= pr * pr * st;
  }
  const float outscale = factor * P.SCALE;

  const float BETAc  = P.BETA;
  const float MUc    = P.MU;
  const float E0EPSc = P.E0EPS;

  // broadcast packs for f32x2 math
  const u64 px0 = pk2(px[0], px[0]), px1 = pk2(px[1], px[1]), px2_ = pk2(px[2], px[2]);
  const u64 py0 = pk2(py[0], py[0]), py1 = pk2(py[1], py[1]), py2_ = pk2(py[2], py[2]);
  const u64 pz0 = pk2(pz[0], pz[0]), pz1 = pk2(pz[1], pz[1]), pz2_ = pk2(pz[2], pz[2]);
  const u64 KF2 = pk2(P.KF, P.KF);

  // ---- leaf evaluation with ASAP group closing ----
  // t[o][g] live only between first and last member of group g in the sequence;
  // closed groups fold into sum[o] immediately (FFMA).
  float t[3][NGRP];
  float sum0 = 0.f, sum1 = 0.f, sum2 = 0.f;

  #pragma unroll
  for (int j = 0; j < NLEAF / 2; ++j) {
    const int k = 2 * j;
    const u64 lb0 = *reinterpret_cast<const u64*>(&s_lb0[k]);   // LDS.64 pair
    const u64 lb1 = *reinterpret_cast<const u64*>(&s_lb1[k]);
    const u64 lb2 = *reinterpret_cast<const u64*>(&s_lb2[k]);
    const u64 lb3 = *reinterpret_cast<const u64*>(&s_lb3[k]);
    const int2 mp = *reinterpret_cast<const int2*>(&s_meta[k]);

    const u64 kqx2 = fma2(px2_, lb3, fma2(px1, lb2, fma2(px0, lb1, mul2(KF2, lb0))));
    const u64 kqy2 = fma2(py2_, lb3, fma2(py1, lb2, mul2(py0, lb1)));
    const u64 kqz2 = fma2(pz2_, lb3, fma2(pz1, lb2, mul2(pz0, lb1)));
    const u64 kq22 = fma2(kqx2, kqx2, fma2(kqy2, kqy2, mul2(kqz2, kqz2)));

    float kqxA, kqxB, kq2A, kq2B, lb0A, lb0B;
    upk2(kqx2, kqxA, kqxB);
    upk2(kq22, kq2A, kq2B);
    upk2(lb0,  lb0A, lb0B);

    const float vA = leaf_eval(kqxA, kq2A, mp.x, lb0A, v0, v1, BETAc, MUc, E0EPSc, s_lv0, k);
    const float vB = leaf_eval(kqxB, kq2B, mp.y, lb0B, v0, v1, BETAc, MUc, E0EPSc, s_lv0, k + 1);

    #pragma unroll
    for (int o = 0; o < 3; ++o) {
      float& so = (o == 0) ? sum0 : ((o == 1) ? sum1 : sum2);
      {
        const int g = SQ.grp[o][k];
        if (SQ.first[o][k])      t[o][g] = vA;
        else if (SQ.last[o][k])  so = fmaf(t[o][g], vA, so);
        else                     t[o][g] *= vA;
      }
      {
        const int g = SQ.grp[o][k + 1];
        if (SQ.first[o][k + 1])     t[o][g] = vB;
        else if (SQ.last[o][k + 1]) so = fmaf(t[o][g], vB, so);
        else                        t[o][g] *= vB;
      }
    }
  }

  // ---- phase weighting ----
  const float ph1 = __cosf(P.PIB * v0);
  const float ph2 = __cosf(P.PIB * v1);
  const float total = fmaf(sum2, ph2, fmaf(sum1, ph1, sum0));

  if (b < batch)
    out[b] = total * outscale;
}

// ---------------- host side ----------------

extern "C" void kernel_launch(void* const* d_in, const int* in_sizes, int n_in,
                              void* d_out, int out_size)
{
  const float* var       = (const float*)d_in[0];
  // d_in[1] = root (unused by the reference)
  const int*   lftype    = (const int*)  d_in[2];
  const int*   lforders  = (const int*)  d_in[3];
  const int*   taui      = (const int*)  d_in[4];
  const int*   tauo      = (const int*)  d_in[5];
  const int*   momidx    = (const int*)  d_in[6];
  const float* loopBasis = (const float*)d_in[7];
  const float* lv0       = (const float*)d_in[8];
  float*       out       = (float*)d_out;

  const int batch = in_sizes[0] / NVAR;

  const double pi   = 3.14159265358979323846;
  const double kf   = pow(9.0 * pi / (2.0 * 2.0), 1.0 / 3.0) / 2.0;  // SPIN = 2
  const double ef   = kf * kf;                                        // KF^2/(2*ME), ME=0.5
  const double beta = 10.0 / ef;
  const double maxk = 10.0 * kf;

  KParams P;
  P.KF    = (float)kf;
  P.MAXK  = (float)maxk;
  P.BETA  = (float)beta;
  P.MU    = (float)(0.99177533 * ef);
  P.E0EPS = (float)(8.0 * pi);                                        // E0^2/EPS0 = 2*4pi
  P.SCALE = (float)(pow(maxk * 2.0 * pi * pi, 3.0) * beta * beta / pow(2.0 * pi, 9.0));
  P.PIB   = (float)(pi / beta);

  const int grid = (batch + BLOCK - 1) / BLOCK;
  feyn_kernel<<<grid, BLOCK>>>(var, lftype, lforders, taui, tauo, momidx,
                               loopBasis, lv0, out, batch, P);
}